// round 12
// baseline (speedup 1.0000x reference)
#include <cuda_runtime.h>

#define NB       262144
#define THREADS  256
#define ROWS_PER_TILE 128
#define NTILES   (NB / ROWS_PER_TILE)   // 2048
#define GRID_X   296                     // 2 CTAs per SM

typedef unsigned long long u64;

// ---- packed f32x2 helpers (SASS FFMA2) ----
__device__ __forceinline__ u64 ffma2(u64 a, u64 b, u64 c) {
    u64 d;
    asm("fma.rn.f32x2 %0, %1, %2, %3;" : "=l"(d) : "l"(a), "l"(b), "l"(c));
    return d;
}
__device__ __forceinline__ u64 pack2(float lo, float hi) {
    u64 d;
    asm("mov.b64 %0, {%1, %2};" : "=l"(d) : "f"(lo), "f"(hi));
    return d;
}
__device__ __forceinline__ void unpack2(u64 a, float& lo, float& hi) {
    asm("mov.b64 {%0, %1}, %2;" : "=f"(lo), "=f"(hi) : "l"(a));
}
__device__ __forceinline__ float hsum2(u64 a) {
    float lo, hi; unpack2(a, lo, hi); return lo + hi;
}

// ---- smem layout (u64 units) ----
// WfP [0,6144)      : WfP[l][k][p] = {W_l[2p][k+1], W_l[2p+1][k+1]}
//                     (serves forward [k][p] AND backward [k_out][v] via j-pairing)
// S0  [6144,10240)  : u64 scr0[32 pair-units][128 rows]   (32 KB)
// S1  [10240,14336) : u64 scr1[32 pair-units][128 rows]
#define U_WF  0
#define U_S0  6144
#define U_S1  10240
#define SMEM_BYTES (14336 * 8)   // 114,688 B -> 2 CTAs/SM

__global__ void __launch_bounds__(THREADS, 2)
odefunc_kernel(const float* __restrict__ t_p,
               const float* __restrict__ z,
               const float* __restrict__ e,
               const float* __restrict__ W0g, const float* __restrict__ b0g,
               const float* __restrict__ W1g, const float* __restrict__ b1g,
               const float* __restrict__ W2g, const float* __restrict__ b2g,
               float* __restrict__ out)
{
    extern __shared__ __align__(16) u64 sm[];

    const int tid = threadIdx.x;
    const int jo  = tid >> 5;        // warp id = output eighth (units jo*8 .. jo*8+7)
    const int r   = tid & 31;        // base row; rows are r + 32*rr, rr=0..3
    const float t = t_p[0];

    // ---- one-time weight staging (forward layout only) ----
    {
        float* WfF = reinterpret_cast<float*>(sm + U_WF);
        const float* Wg[3] = { W0g, W1g, W2g };
#pragma unroll 1
        for (int l = 0; l < 3; ++l) {
            for (int idx = tid; idx < 4096; idx += THREADS) {
                int j = idx >> 6, k = idx & 63;
                WfF[((l * 64 + k) * 32 + (j >> 1)) * 2 + (j & 1)] = Wg[l][j * 65 + k + 1];
            }
        }
    }
    __syncthreads();

    const u64 tt = pack2(t, t);
    u64 acc[32];                        // fwd uses [rr*4+q] (16), bwd uses [rr*8+kk] (32)
    unsigned mask0 = 0u, mask1 = 0u;    // bit (rr*8 + 2i (+1))

    for (int tile = blockIdx.x; tile < NTILES; tile += GRID_X) {
        const size_t rowbase = (size_t)tile * ROWS_PER_TILE;

        __syncthreads();   // prev tile's div-combine readers done with S0

        // ---- stage z: this thread's 8-float slice of its 4 rows into S0 ----
#pragma unroll
        for (int rr = 0; rr < 4; ++rr) {
            const int rloc = r + 32 * rr;
            const ulonglong2* zp =
                reinterpret_cast<const ulonglong2*>(z + (rowbase + rloc) * 64 + jo * 8);
            ulonglong2 v0 = zp[0], v1 = zp[1];
            sm[U_S0 + (jo * 4 + 0) * 128 + rloc] = v0.x;
            sm[U_S0 + (jo * 4 + 1) * 128 + rloc] = v0.y;
            sm[U_S0 + (jo * 4 + 2) * 128 + rloc] = v1.x;
            sm[U_S0 + (jo * 4 + 3) * 128 + rloc] = v1.y;
        }

        // ---- six passes: fwd L0,L1,L2 then bwd B2,B1,B0 ----
#pragma unroll 1
        for (int pass = 0; pass < 6; ++pass) {
            __syncthreads();   // pass inputs visible

            const u64* sin  = sm + ((pass & 1) ? U_S1 : U_S0);
            u64*       sout = sm + ((pass & 1) ? U_S0 : U_S1);

            if (pass < 3) {
                // ================= FORWARD (bit-exact serial-k chain) =================
                const float* Wt = (pass == 0) ? W0g : (pass == 1) ? W1g : W2g;
                // init: acc_j = fma(t, W[j][0], 0)
#pragma unroll
                for (int q = 0; q < 4; ++q) {
                    int j0 = jo * 8 + 2 * q;
                    u64 tc  = pack2(Wt[j0 * 65], Wt[(j0 + 1) * 65]);
                    u64 ini = ffma2(tt, tc, 0ull);
#pragma unroll
                    for (int rr = 0; rr < 4; ++rr) acc[rr * 4 + q] = ini;
                }
                const u64* W = sm + U_WF + pass * 2048;
#pragma unroll 4
                for (int u = 0; u < 32; ++u) {
                    u64 hlo[4], hhi[4];
#pragma unroll
                    for (int rr = 0; rr < 4; ++rr) {
                        u64 hp = sin[u * 128 + r + 32 * rr];   // {h_2u, h_2u+1}
                        float lo, hi; unpack2(hp, lo, hi);
                        hlo[rr] = pack2(lo, lo);
                        hhi[rr] = pack2(hi, hi);
                    }
                    const ulonglong2* w0 =
                        reinterpret_cast<const ulonglong2*>(W + (2 * u)     * 32 + jo * 4);
                    const ulonglong2* w1 =
                        reinterpret_cast<const ulonglong2*>(W + (2 * u + 1) * 32 + jo * 4);
#pragma unroll
                    for (int q = 0; q < 2; ++q) {        // k = 2u
                        ulonglong2 w = w0[q];
#pragma unroll
                        for (int rr = 0; rr < 4; ++rr) {
                            acc[rr * 4 + 2 * q]     = ffma2(hlo[rr], w.x, acc[rr * 4 + 2 * q]);
                            acc[rr * 4 + 2 * q + 1] = ffma2(hlo[rr], w.y, acc[rr * 4 + 2 * q + 1]);
                        }
                    }
#pragma unroll
                    for (int q = 0; q < 2; ++q) {        // k = 2u+1
                        ulonglong2 w = w1[q];
#pragma unroll
                        for (int rr = 0; rr < 4; ++rr) {
                            acc[rr * 4 + 2 * q]     = ffma2(hhi[rr], w.x, acc[rr * 4 + 2 * q]);
                            acc[rr * 4 + 2 * q + 1] = ffma2(hhi[rr], w.y, acc[rr * 4 + 2 * q + 1]);
                        }
                    }
                }
                // ---- forward epilogues ----
                if (pass < 2) {
                    const float* bsel = (pass == 0) ? b0g : b1g;
                    unsigned m = 0u;
#pragma unroll
                    for (int i = 0; i < 4; ++i) {
                        u64 bp = *reinterpret_cast<const u64*>(bsel + jo * 8 + 2 * i);
                        float b0, b1; unpack2(bp, b0, b1);
#pragma unroll
                        for (int rr = 0; rr < 4; ++rr) {
                            float v0, v1; unpack2(acc[rr * 4 + i], v0, v1);
                            v0 += b0; v1 += b1;
                            m |= (unsigned)(v0 > 0.0f) << (rr * 8 + 2 * i);
                            m |= (unsigned)(v1 > 0.0f) << (rr * 8 + 2 * i + 1);
                            sout[(jo * 4 + i) * 128 + r + 32 * rr] =
                                pack2(fmaxf(v0, 0.0f), fmaxf(v1, 0.0f));
                        }
                    }
                    if (pass == 0) mask0 = m; else mask1 = m;
                } else {
                    // z_dot -> gmem (bias once), then stage e into sout (= S1)
                    const float4* b4 = reinterpret_cast<const float4*>(b2g + jo * 8);
                    float4 ba = b4[0], bb = b4[1];
#pragma unroll
                    for (int rr = 0; rr < 4; ++rr) {
                        const int rloc = r + 32 * rr;
                        float4* o4 = reinterpret_cast<float4*>(out + (rowbase + rloc) * 64 + jo * 8);
                        float v0, v1, v2, v3;
                        unpack2(acc[rr * 4 + 0], v0, v1);
                        unpack2(acc[rr * 4 + 1], v2, v3);
                        o4[0] = make_float4(v0 + ba.x, v1 + ba.y, v2 + ba.z, v3 + ba.w);
                        unpack2(acc[rr * 4 + 2], v0, v1);
                        unpack2(acc[rr * 4 + 3], v2, v3);
                        o4[1] = make_float4(v0 + bb.x, v1 + bb.y, v2 + bb.z, v3 + bb.w);
                    }
#pragma unroll
                    for (int rr = 0; rr < 4; ++rr) {
                        const int rloc = r + 32 * rr;
                        const ulonglong2* ep =
                            reinterpret_cast<const ulonglong2*>(e + (rowbase + rloc) * 64 + jo * 8);
                        ulonglong2 v0 = ep[0], v1 = ep[1];
                        sout[(jo * 4 + 0) * 128 + rloc] = v0.x;
                        sout[(jo * 4 + 1) * 128 + rloc] = v0.y;
                        sout[(jo * 4 + 2) * 128 + rloc] = v1.x;
                        sout[(jo * 4 + 3) * 128 + rloc] = v1.y;
                    }
                }
            } else {
                // ====== BACKWARD: j-paired reduction, reuses FORWARD weight layout ======
                // acc[rr*8+kk] = {sum over even j, sum over odd j} for output k = jo*8+kk
                const int l = 5 - pass;
                const u64* W = sm + U_WF + l * 2048;
#pragma unroll
                for (int i = 0; i < 32; ++i) acc[i] = 0ull;

#pragma unroll 2
                for (int vv = 0; vv < 16; ++vv) {       // j-pairs v = 2vv, 2vv+1
                    u64 gA[4], gB[4];
#pragma unroll
                    for (int rr = 0; rr < 4; ++rr) {
                        gA[rr] = sin[(2 * vv)     * 128 + r + 32 * rr];  // {g_4vv,  g_4vv+1}
                        gB[rr] = sin[(2 * vv + 1) * 128 + r + 32 * rr];  // {g_4vv+2,g_4vv+3}
                    }
#pragma unroll
                    for (int kk = 0; kk < 8; ++kk) {
                        ulonglong2 w2 = *reinterpret_cast<const ulonglong2*>(
                            W + (jo * 8 + kk) * 32 + 2 * vv);
#pragma unroll
                        for (int rr = 0; rr < 4; ++rr) {
                            acc[rr * 8 + kk] = ffma2(gA[rr], w2.x, acc[rr * 8 + kk]);
                            acc[rr * 8 + kk] = ffma2(gB[rr], w2.y, acc[rr * 8 + kk]);
                        }
                    }
                }

                if (pass < 5) {
                    // combine even/odd partials (order-free), apply relu mask, store pairs
                    unsigned m = (pass == 3) ? mask1 : mask0;
#pragma unroll
                    for (int i = 0; i < 4; ++i) {
#pragma unroll
                        for (int rr = 0; rr < 4; ++rr) {
                            float v0 = hsum2(acc[rr * 8 + 2 * i]);
                            float v1 = hsum2(acc[rr * 8 + 2 * i + 1]);
                            v0 = ((m >> (rr * 8 + 2 * i))     & 1u) ? v0 : 0.0f;
                            v1 = ((m >> (rr * 8 + 2 * i + 1)) & 1u) ? v1 : 0.0f;
                            sout[(jo * 4 + i) * 128 + r + 32 * rr] = pack2(v0, v1);
                        }
                    }
                } else {
                    // B0: gin = combine; partial div over this thread's 8 k's; combine via S0
                    float* partial = reinterpret_cast<float*>(sout);   // sout = S0 on pass 5
#pragma unroll
                    for (int rr = 0; rr < 4; ++rr) {
                        const int rloc = r + 32 * rr;
                        const float4* e4 =
                            reinterpret_cast<const float4*>(e + (rowbase + rloc) * 64 + jo * 8);
                        float4 ea = e4[0], eb = e4[1];
                        float s = 0.0f;
                        s = fmaf(hsum2(acc[rr * 8 + 0]), ea.x, s);
                        s = fmaf(hsum2(acc[rr * 8 + 1]), ea.y, s);
                        s = fmaf(hsum2(acc[rr * 8 + 2]), ea.z, s);
                        s = fmaf(hsum2(acc[rr * 8 + 3]), ea.w, s);
                        s = fmaf(hsum2(acc[rr * 8 + 4]), eb.x, s);
                        s = fmaf(hsum2(acc[rr * 8 + 5]), eb.y, s);
                        s = fmaf(hsum2(acc[rr * 8 + 6]), eb.z, s);
                        s = fmaf(hsum2(acc[rr * 8 + 7]), eb.w, s);
                        partial[jo * 128 + rloc] = s;
                    }
                    __syncthreads();
                    if (jo == 0) {
#pragma unroll
                        for (int rr = 0; rr < 4; ++rr) {
                            const int rloc = r + 32 * rr;
                            float s = 0.0f;
#pragma unroll
                            for (int g = 0; g < 8; ++g)
                                s += partial[g * 128 + rloc];
                            out[(size_t)NB * 64 + rowbase + rloc] = -s;
                        }
                    }
                }
            }
        }
    }
}

extern "C" void kernel_launch(void* const* d_in, const int* in_sizes, int n_in,
                              void* d_out, int out_size) {
    const float* t  = (const float*)d_in[0];
    const float* z  = (const float*)d_in[1];
    const float* e  = (const float*)d_in[2];
    const float* W0 = (const float*)d_in[3];
    const float* b0 = (const float*)d_in[4];
    const float* W1 = (const float*)d_in[5];
    const float* b1 = (const float*)d_in[6];
    const float* W2 = (const float*)d_in[7];
    const float* b2 = (const float*)d_in[8];
    float* out = (float*)d_out;

    cudaFuncSetAttribute(odefunc_kernel,
                         cudaFuncAttributeMaxDynamicSharedMemorySize, SMEM_BYTES);

    odefunc_kernel<<<GRID_X, THREADS, SMEM_BYTES>>>(t, z, e, W0, b0, W1, b1, W2, b2, out);
}

// round 14
// speedup vs baseline: 1.2129x; 1.2129x over previous
#include <cuda_runtime.h>

#define NB       262144
#define THREADS  256
#define ROWS_PER_TILE 128
#define NTILES   (NB / ROWS_PER_TILE)   // 2048
#define GRID_X   148

typedef unsigned long long u64;

// ---- packed f32x2 helpers (SASS FFMA2) ----
__device__ __forceinline__ u64 ffma2(u64 a, u64 b, u64 c) {
    u64 d;
    asm("fma.rn.f32x2 %0, %1, %2, %3;" : "=l"(d) : "l"(a), "l"(b), "l"(c));
    return d;
}
__device__ __forceinline__ u64 pack2(float lo, float hi) {
    u64 d;
    asm("mov.b64 %0, {%1, %2};" : "=l"(d) : "f"(lo), "f"(hi));
    return d;
}
__device__ __forceinline__ void unpack2(u64 a, float& lo, float& hi) {
    asm("mov.b64 {%0, %1}, %2;" : "=f"(lo), "=f"(hi) : "l"(a));
}
__device__ __forceinline__ float hsum2(u64 a) {
    float lo, hi; unpack2(a, lo, hi); return lo + hi;
}

// ---- smem layout (u64 units) ----
// WfP [0,6144)       : WfP[l][k][p] = {W_l[2p][k+1], W_l[2p+1][k+1]}
// H0  [6144,10240)   : u64 h-scratch A [32 pair-units][128 rows]
// H1  [10240,14336)  : u64 h-scratch B (also reused as float partial[8][128] in div combine)
// V0  [14336,18432)  : u64 v-scratch A
// V1  [18432,22528)  : u64 v-scratch B
#define U_WF  0
#define U_H0  6144
#define U_H1  10240
#define U_V0  14336
#define U_V1  18432
#define SMEM_BYTES (22528 * 8)   // 180,224 B

__global__ void __launch_bounds__(THREADS, 1)
odefunc_kernel(const float* __restrict__ t_p,
               const float* __restrict__ z,
               const float* __restrict__ e,
               const float* __restrict__ W0g, const float* __restrict__ b0g,
               const float* __restrict__ W1g, const float* __restrict__ b1g,
               const float* __restrict__ W2g, const float* __restrict__ b2g,
               float* __restrict__ out)
{
    extern __shared__ __align__(16) u64 sm[];

    const int tid = threadIdx.x;
    const int jo  = tid >> 5;        // warp id: owns pairs jo*4 .. jo*4+3 (outputs jo*8..jo*8+7)
    const int r   = tid & 31;        // base row; rows r + 32*rr, rr=0..3
    const float t = t_p[0];

    // ---- one-time weight staging (forward layout only; proven R7..R12) ----
    {
        float* WfF = reinterpret_cast<float*>(sm + U_WF);
        const float* Wg[3] = { W0g, W1g, W2g };
#pragma unroll 1
        for (int l = 0; l < 3; ++l) {
            for (int idx = tid; idx < 4096; idx += THREADS) {
                int j = idx >> 6, k = idx & 63;
                WfF[((l * 64 + k) * 32 + (j >> 1)) * 2 + (j & 1)] = Wg[l][j * 65 + k + 1];
            }
        }
    }
    __syncthreads();

    const u64 tt = pack2(t, t);
    u64 ah[4][4], av[4][4];          // [row rr][pair i]: primal h and tangent v accumulators

    for (int tile = blockIdx.x; tile < NTILES; tile += GRID_X) {
        const size_t rowbase = (size_t)tile * ROWS_PER_TILE;

        __syncthreads();   // prev tile's pass-2 readers done with H0/V0

        // ---- stage z -> H0 and e -> V0 (tangent of [t,z] in direction e is [0,e]) ----
#pragma unroll
        for (int rr = 0; rr < 4; ++rr) {
            const int rloc = r + 32 * rr;
            const ulonglong2* zp =
                reinterpret_cast<const ulonglong2*>(z + (rowbase + rloc) * 64 + jo * 8);
            ulonglong2 z0 = zp[0], z1 = zp[1];
            sm[U_H0 + (jo * 4 + 0) * 128 + rloc] = z0.x;
            sm[U_H0 + (jo * 4 + 1) * 128 + rloc] = z0.y;
            sm[U_H0 + (jo * 4 + 2) * 128 + rloc] = z1.x;
            sm[U_H0 + (jo * 4 + 3) * 128 + rloc] = z1.y;
            const ulonglong2* ep =
                reinterpret_cast<const ulonglong2*>(e + (rowbase + rloc) * 64 + jo * 8);
            ulonglong2 e0 = ep[0], e1 = ep[1];
            sm[U_V0 + (jo * 4 + 0) * 128 + rloc] = e0.x;
            sm[U_V0 + (jo * 4 + 1) * 128 + rloc] = e0.y;
            sm[U_V0 + (jo * 4 + 2) * 128 + rloc] = e1.x;
            sm[U_V0 + (jo * 4 + 3) * 128 + rloc] = e1.y;
        }

        // ---- three fused primal+tangent passes ----
#pragma unroll 1
        for (int pass = 0; pass < 3; ++pass) {
            __syncthreads();

            const u64* hin  = sm + ((pass & 1) ? U_H1 : U_H0);
            u64*       hout = sm + ((pass & 1) ? U_H0 : U_H1);
            const u64* vin  = sm + ((pass & 1) ? U_V1 : U_V0);
            u64*       vout = sm + ((pass & 1) ? U_V0 : U_V1);
            const u64* W    = sm + U_WF + pass * 2048;
            const float* Wt = (pass == 0) ? W0g : (pass == 1) ? W1g : W2g;

            // init: h gets the k=0 term fma(t, W[:,0], 0); v-tangent of t is 0
#pragma unroll
            for (int i = 0; i < 4; ++i) {
                int j0 = jo * 8 + 2 * i;
                u64 ini = ffma2(tt, pack2(Wt[j0 * 65], Wt[(j0 + 1) * 65]), 0ull);
#pragma unroll
                for (int rr = 0; rr < 4; ++rr) { ah[rr][i] = ini; av[rr][i] = 0ull; }
            }

            // mainloop: k = 2u, 2u+1 strictly ascending (h chain bit-exact serial)
#pragma unroll 4
            for (int u = 0; u < 32; ++u) {
                u64 hlo[4], hhi[4], vlo[4], vhi[4];
#pragma unroll
                for (int rr = 0; rr < 4; ++rr) {
                    float lo, hi;
                    unpack2(hin[u * 128 + r + 32 * rr], lo, hi);
                    hlo[rr] = pack2(lo, lo);  hhi[rr] = pack2(hi, hi);
                    unpack2(vin[u * 128 + r + 32 * rr], lo, hi);
                    vlo[rr] = pack2(lo, lo);  vhi[rr] = pack2(hi, hi);
                }
                const ulonglong2* w0 =
                    reinterpret_cast<const ulonglong2*>(W + (2 * u)     * 32 + jo * 4);
                const ulonglong2* w1 =
                    reinterpret_cast<const ulonglong2*>(W + (2 * u + 1) * 32 + jo * 4);
#pragma unroll
                for (int q = 0; q < 2; ++q) {          // k = 2u
                    ulonglong2 w = w0[q];
#pragma unroll
                    for (int rr = 0; rr < 4; ++rr) {
                        ah[rr][2*q]   = ffma2(hlo[rr], w.x, ah[rr][2*q]);
                        ah[rr][2*q+1] = ffma2(hlo[rr], w.y, ah[rr][2*q+1]);
                        av[rr][2*q]   = ffma2(vlo[rr], w.x, av[rr][2*q]);
                        av[rr][2*q+1] = ffma2(vlo[rr], w.y, av[rr][2*q+1]);
                    }
                }
#pragma unroll
                for (int q = 0; q < 2; ++q) {          // k = 2u+1
                    ulonglong2 w = w1[q];
#pragma unroll
                    for (int rr = 0; rr < 4; ++rr) {
                        ah[rr][2*q]   = ffma2(hhi[rr], w.x, ah[rr][2*q]);
                        ah[rr][2*q+1] = ffma2(hhi[rr], w.y, ah[rr][2*q+1]);
                        av[rr][2*q]   = ffma2(vhi[rr], w.x, av[rr][2*q]);
                        av[rr][2*q+1] = ffma2(vhi[rr], w.y, av[rr][2*q+1]);
                    }
                }
            }

            // ---- epilogues ----
            if (pass < 2) {
                // bias once (bit-exact), relu on h, relu-mask applied to v in-register
                const float* bsel = (pass == 0) ? b0g : b1g;
#pragma unroll
                for (int i = 0; i < 4; ++i) {
                    u64 bp = *reinterpret_cast<const u64*>(bsel + jo * 8 + 2 * i);
                    float b0, b1; unpack2(bp, b0, b1);
#pragma unroll
                    for (int rr = 0; rr < 4; ++rr) {
                        float h0, h1; unpack2(ah[rr][i], h0, h1);
                        float v0, v1; unpack2(av[rr][i], v0, v1);
                        h0 += b0; h1 += b1;
                        v0 = (h0 > 0.0f) ? v0 : 0.0f;
                        v1 = (h1 > 0.0f) ? v1 : 0.0f;
                        hout[(jo * 4 + i) * 128 + r + 32 * rr] =
                            pack2(fmaxf(h0, 0.0f), fmaxf(h1, 0.0f));
                        vout[(jo * 4 + i) * 128 + r + 32 * rr] = pack2(v0, v1);
                    }
                }
            } else {
                // z_dot = h + b2 -> gmem; div partial = dot(v, e-slice)
                const float4* b4 = reinterpret_cast<const float4*>(b2g + jo * 8);
                float4 ba = b4[0], bb = b4[1];
                float* partial = reinterpret_cast<float*>(sm + U_H1);  // [8 jo][128 rows]
#pragma unroll
                for (int rr = 0; rr < 4; ++rr) {
                    const int rloc = r + 32 * rr;
                    float4* o4 = reinterpret_cast<float4*>(out + (rowbase + rloc) * 64 + jo * 8);
                    float v0, v1, v2, v3;
                    unpack2(ah[rr][0], v0, v1);
                    unpack2(ah[rr][1], v2, v3);
                    o4[0] = make_float4(v0 + ba.x, v1 + ba.y, v2 + ba.z, v3 + ba.w);
                    unpack2(ah[rr][2], v0, v1);
                    unpack2(ah[rr][3], v2, v3);
                    o4[1] = make_float4(v0 + bb.x, v1 + bb.y, v2 + bb.z, v3 + bb.w);

                    const ulonglong2* ep =
                        reinterpret_cast<const ulonglong2*>(e + (rowbase + rloc) * 64 + jo * 8);
                    ulonglong2 e0 = ep[0], e1 = ep[1];
                    u64 d = 0ull;
                    d = ffma2(e0.x, av[rr][0], d);
                    d = ffma2(e0.y, av[rr][1], d);
                    d = ffma2(e1.x, av[rr][2], d);
                    d = ffma2(e1.y, av[rr][3], d);
                    partial[jo * 128 + rloc] = hsum2(d);
                }
            }
        }

        __syncthreads();
        if (jo == 0) {
            const float* partial = reinterpret_cast<const float*>(sm + U_H1);
#pragma unroll
            for (int rr = 0; rr < 4; ++rr) {
                const int rloc = r + 32 * rr;
                float s = 0.0f;
#pragma unroll
                for (int g = 0; g < 8; ++g)
                    s += partial[g * 128 + rloc];
                out[(size_t)NB * 64 + rowbase + rloc] = -s;
            }
        }
    }
}

extern "C" void kernel_launch(void* const* d_in, const int* in_sizes, int n_in,
                              void* d_out, int out_size) {
    const float* t  = (const float*)d_in[0];
    const float* z  = (const float*)d_in[1];
    const float* e  = (const float*)d_in[2];
    const float* W0 = (const float*)d_in[3];
    const float* b0 = (const float*)d_in[4];
    const float* W1 = (const float*)d_in[5];
    const float* b1 = (const float*)d_in[6];
    const float* W2 = (const float*)d_in[7];
    const float* b2 = (const float*)d_in[8];
    float* out = (float*)d_out;

    cudaFuncSetAttribute(odefunc_kernel,
                         cudaFuncAttributeMaxDynamicSharedMemorySize, SMEM_BYTES);

    odefunc_kernel<<<GRID_X, THREADS, SMEM_BYTES>>>(t, z, e, W0, b0, W1, b1, W2, b2, out);
}